// round 2
// baseline (speedup 1.0000x reference)
#include <cuda_runtime.h>
#include <math.h>

#define HIDDEN 150
#define EMBED 300
#define OUTC 5
#define DEPTH 13
#define NN 8191          // 2^13 - 1
#define LL 4096          // leaves
#define LEAF_START 4095  // 2^12 - 1

// ---------------- device scratch (no allocs allowed) ----------------
__device__ float g_H[NN * HIDDEN];
__device__ float g_C[NN * HIDDEN];
// gate-interleaved stacked weights: row n = j*GATES + gate, each row 300 wide
__device__ float g_WLi[450 * EMBED];   // leaf: gates {i,o,u}, GATES=3
__device__ float g_WUi[750 * EMBED];   // inner: gates {i,fl,fr,o,u}, GATES=5
__device__ float g_bLi[450];
__device__ float g_bUi[750];

__device__ __forceinline__ float sigmoidf(float x) {
    return 1.0f / (1.0f + expf(-x));
}

// ---------------- weight stacking (gate-interleaved) ----------------
__global__ void prep_kernel(
    const float* __restrict__ Wi, const float* __restrict__ bi,
    const float* __restrict__ Wo, const float* __restrict__ bo,
    const float* __restrict__ Wu, const float* __restrict__ bu,
    const float* __restrict__ U0i, const float* __restrict__ U1i, const float* __restrict__ bbi,
    const float* __restrict__ U00f, const float* __restrict__ U01f,
    const float* __restrict__ U10f, const float* __restrict__ U11f, const float* __restrict__ bbf,
    const float* __restrict__ U0o, const float* __restrict__ U1o, const float* __restrict__ bbo,
    const float* __restrict__ U0u, const float* __restrict__ U1u, const float* __restrict__ bbu)
{
    int t = blockIdx.x * blockDim.x + threadIdx.x;
    int stride = gridDim.x * blockDim.x;

    // leaf weights: n = j*3 + g ; g: 0=i, 1=o, 2=u
    for (int idx = t; idx < 450 * EMBED; idx += stride) {
        int n = idx / EMBED, k = idx % EMBED;
        int j = n / 3, g = n % 3;
        const float* W = (g == 0) ? Wi : (g == 1) ? Wo : Wu;
        g_WLi[idx] = W[j * EMBED + k];
    }
    // inner weights: n = j*5 + g ; g: 0=i, 1=fl, 2=fr, 3=o, 4=u ; cols = [U0 | U1]
    for (int idx = t; idx < 750 * EMBED; idx += stride) {
        int n = idx / EMBED, k = idx % EMBED;
        int j = n / 5, g = n % 5;
        const float* U0; const float* U1;
        switch (g) {
            case 0:  U0 = U0i;  U1 = U1i;  break;
            case 1:  U0 = U00f; U1 = U01f; break;
            case 2:  U0 = U10f; U1 = U11f; break;
            case 3:  U0 = U0o;  U1 = U1o;  break;
            default: U0 = U0u;  U1 = U1u;  break;
        }
        g_WUi[idx] = (k < HIDDEN) ? U0[j * HIDDEN + k] : U1[j * HIDDEN + (k - HIDDEN)];
    }
    if (t < 450) {
        int j = t / 3, g = t % 3;
        g_bLi[t] = (g == 0) ? bi[j] : (g == 1) ? bo[j] : bu[j];
    }
    if (t < 750) {
        int j = t / 5, g = t % 5;
        g_bUi[t] = (g == 0) ? bbi[j] : (g <= 2) ? bbf[j] : (g == 3) ? bbo[j] : bbu[j];
    }
}

// ---------------- fused GEMM + gate activation ----------------
// MODE 0 (leaf):  A row m = word_embedding[words[LEAF_START+m]] (K=300), W = g_WLi (GATES=3)
// MODE 1 (inner): A row m = [h(2n+1) | h(2n+2)] = contiguous slice of g_H (K=300), W = g_WUi (GATES=5)
//
// Block: 256 threads as (tx=16, ty=16). Thread tile: 4 rows x 2 j's x GATES.
// BM=64 rows, BJ=32 j's per block, grid = (ceil(M/64), ceil(150/32)=5)

#define BM 64
#define BJ 32
#define BK 20   // 300 = 15 * 20

template<int GATES, int MODE>
__global__ __launch_bounds__(256)
void fused_level(int s, int M,
                 const float* __restrict__ emb,
                 const int* __restrict__ words)
{
    const int NCOLS = BJ * GATES;             // 96 (leaf) or 160 (inner)
    __shared__ float As[BK][BM];
    __shared__ float Ws[BK][BJ * GATES];
    __shared__ int   rowOff[BM];              // offsets into A source (in floats), -1 = invalid

    const float* __restrict__ W = (MODE == 0) ? g_WLi : g_WUi;
    const float* __restrict__ Abase = (MODE == 0) ? emb : (g_H + (2 * s + 1) * HIDDEN);
    const float* __restrict__ bias = (MODE == 0) ? g_bLi : g_bUi;

    int bm = blockIdx.x * BM;
    int j0 = blockIdx.y * BJ;
    int n0 = j0 * GATES;
    int tid = threadIdx.x;
    int tx = tid & 15, ty = tid >> 4;

    if (tid < BM) {
        int m = bm + tid;
        int off = -1;
        if (m < M) {
            if (MODE == 0) off = words[LEAF_START + m] * EMBED;
            else           off = m * EMBED;  // [lh|rh] contiguous, lda=300
        }
        rowOff[tid] = off;
    }
    __syncthreads();

    float acc[4][2][GATES];
    #pragma unroll
    for (int i = 0; i < 4; i++)
        #pragma unroll
        for (int jj = 0; jj < 2; jj++)
            #pragma unroll
            for (int g = 0; g < GATES; g++)
                acc[i][jj][g] = 0.0f;

    for (int k0 = 0; k0 < EMBED; k0 += BK) {
        // A tile: BM x BK = 1280 elems, 5 per thread
        #pragma unroll
        for (int l = 0; l < 5; l++) {
            int e = tid + l * 256;
            int ml = e / BK, kk = e % BK;
            int off = rowOff[ml];
            As[kk][ml] = (off >= 0) ? Abase[off + k0 + kk] : 0.0f;
        }
        // W tile: NCOLS x BK
        const int WELEMS = NCOLS * BK;
        #pragma unroll
        for (int l = 0; l < (WELEMS + 255) / 256; l++) {
            int e = tid + l * 256;
            if (e < WELEMS) {
                int nl = e / BK, kk = e % BK;
                int n = n0 + nl;
                Ws[kk][nl] = (n < HIDDEN * GATES) ? W[n * EMBED + k0 + kk] : 0.0f;
            }
        }
        __syncthreads();

        #pragma unroll
        for (int kk = 0; kk < BK; kk++) {
            float a[4];
            float w[2][GATES];
            #pragma unroll
            for (int i = 0; i < 4; i++) a[i] = As[kk][ty * 4 + i];
            #pragma unroll
            for (int jj = 0; jj < 2; jj++)
                #pragma unroll
                for (int g = 0; g < GATES; g++)
                    w[jj][g] = Ws[kk][(tx * 2 + jj) * GATES + g];
            #pragma unroll
            for (int i = 0; i < 4; i++)
                #pragma unroll
                for (int jj = 0; jj < 2; jj++)
                    #pragma unroll
                    for (int g = 0; g < GATES; g++)
                        acc[i][jj][g] += a[i] * w[jj][g];
        }
        __syncthreads();
    }

    // fused activation epilogue
    #pragma unroll
    for (int i = 0; i < 4; i++) {
        int m = bm + ty * 4 + i;
        if (m >= M) continue;
        #pragma unroll
        for (int jj = 0; jj < 2; jj++) {
            int j = j0 + tx * 2 + jj;
            if (j >= HIDDEN) continue;
            int nb = j * GATES;
            if (MODE == 0) {
                float ig = sigmoidf(acc[i][jj][0] + bias[nb + 0]);
                float og = sigmoidf(acc[i][jj][1] + bias[nb + 1]);
                float uv = tanhf   (acc[i][jj][2] + bias[nb + 2]);
                float c = ig * uv;
                float h = og * tanhf(c);
                int node = LEAF_START + m;
                g_H[node * HIDDEN + j] = h;
                g_C[node * HIDDEN + j] = c;
            } else {
                float ig = sigmoidf(acc[i][jj][0] + bias[nb + 0]);
                float fl = sigmoidf(acc[i][jj][1] + bias[nb + 1]);
                float fr = sigmoidf(acc[i][jj][2] + bias[nb + 2]);
                float og = sigmoidf(acc[i][jj][3] + bias[nb + 3]);
                float uv = tanhf   (acc[i][jj][4] + bias[nb + 4]);
                int node = s + m;
                float lc = g_C[(2 * node + 1) * HIDDEN + j];
                float rc = g_C[(2 * node + 2) * HIDDEN + j];
                float c = ig * uv + fl * lc + fr * rc;
                float h = og * tanhf(c);
                g_H[node * HIDDEN + j] = h;
                g_C[node * HIDDEN + j] = c;
            }
        }
    }
}

// ---------------- loss ----------------
__global__ void zero_out(float* out)
{
    if (threadIdx.x == 0 && blockIdx.x == 0) out[0] = 0.0f;
}

__global__ void loss_kernel(const float* __restrict__ Why,
                            const float* __restrict__ by,
                            const int*   __restrict__ scores,
                            float* __restrict__ out)
{
    int gw   = (blockIdx.x * blockDim.x + threadIdx.x) >> 5;
    int lane = threadIdx.x & 31;
    if (gw >= NN) return;

    const float* h = g_H + gw * HIDDEN;
    float logits[OUTC];
    #pragma unroll
    for (int o = 0; o < OUTC; o++) {
        float sacc = 0.0f;
        for (int k = lane; k < HIDDEN; k += 32)
            sacc += Why[o * HIDDEN + k] * h[k];
        #pragma unroll
        for (int d = 16; d > 0; d >>= 1)
            sacc += __shfl_xor_sync(0xffffffff, sacc, d);
        logits[o] = sacc + by[o];
    }
    if (lane == 0) {
        float mx = logits[0];
        #pragma unroll
        for (int o = 1; o < OUTC; o++) mx = fmaxf(mx, logits[o]);
        float se = 0.0f;
        #pragma unroll
        for (int o = 0; o < OUTC; o++) se += expf(logits[o] - mx);
        float lse = mx + logf(se);
        int sc = scores[gw];
        atomicAdd(out, lse - logits[sc]);
    }
}

// ---------------- launch ----------------
extern "C" void kernel_launch(void* const* d_in, const int* in_sizes, int n_in,
                              void* d_out, int out_size)
{
    const float* Wi   = (const float*)d_in[0];
    const float* bi   = (const float*)d_in[1];
    const float* Wo   = (const float*)d_in[2];
    const float* bo   = (const float*)d_in[3];
    const float* Wu   = (const float*)d_in[4];
    const float* bu   = (const float*)d_in[5];
    const float* U0i  = (const float*)d_in[6];
    const float* U1i  = (const float*)d_in[7];
    const float* bbi  = (const float*)d_in[8];
    const float* U00f = (const float*)d_in[9];
    const float* U01f = (const float*)d_in[10];
    const float* U10f = (const float*)d_in[11];
    const float* U11f = (const float*)d_in[12];
    const float* bbf  = (const float*)d_in[13];
    const float* U0o  = (const float*)d_in[14];
    const float* U1o  = (const float*)d_in[15];
    const float* bbo  = (const float*)d_in[16];
    const float* U0u  = (const float*)d_in[17];
    const float* U1u  = (const float*)d_in[18];
    const float* bbu  = (const float*)d_in[19];
    const float* Why  = (const float*)d_in[20];
    const float* by   = (const float*)d_in[21];
    const float* emb  = (const float*)d_in[22];
    const int*   scores = (const int*)d_in[23];
    const int*   words  = (const int*)d_in[24];
    // d_in[25]=lchs, d_in[26]=rchs — implicit in the perfect-tree layout

    float* out = (float*)d_out;

    zero_out<<<1, 32>>>(out);
    prep_kernel<<<240, 256>>>(Wi, bi, Wo, bo, Wu, bu,
                              U0i, U1i, bbi,
                              U00f, U01f, U10f, U11f, bbf,
                              U0o, U1o, bbo,
                              U0u, U1u, bbu);

    // leaf level: M=4096, GATES=3
    {
        dim3 grid((LL + BM - 1) / BM, (HIDDEN + BJ - 1) / BJ);   // (64, 5)
        fused_level<3, 0><<<grid, 256>>>(0, LL, emb, words);
    }

    // internal levels, bottom-up: GATES=5
    for (int d = DEPTH - 2; d >= 0; d--) {
        int s = (1 << d) - 1;
        int M = 1 << d;
        dim3 grid((M + BM - 1) / BM, (HIDDEN + BJ - 1) / BJ);
        fused_level<5, 1><<<grid, 256>>>(s, M, nullptr, nullptr);
    }

    // final loss over all 8191 nodes
    {
        int threads = 256;
        int warpsPerBlock = threads / 32;
        int blocks = (NN + warpsPerBlock - 1) / warpsPerBlock;
        loss_kernel<<<blocks, threads>>>(Why, by, scores, out);
    }
    (void)in_sizes; (void)n_in; (void)out_size;
}

// round 3
// speedup vs baseline: 2.0724x; 2.0724x over previous
#include <cuda_runtime.h>
#include <math.h>

#define HIDDEN 150
#define EMBED 300
#define OUTC 5
#define DEPTH 13
#define NN 8191          // 2^13 - 1
#define LL 4096          // leaves
#define LEAF_START 4095  // 2^12 - 1
#define BK 20            // 300 = 15 * 20

// ---------------- device scratch (no allocs allowed) ----------------
__device__ float g_H[NN * HIDDEN];
__device__ float g_C[NN * HIDDEN];
// gate-interleaved stacked weights: row n = j*GATES + gate, each row 300 wide
__device__ float g_WLi[450 * EMBED];   // leaf: gates {i,o,u}, GATES=3
__device__ float g_WUi[750 * EMBED];   // inner: gates {i,fl,fr,o,u}, GATES=5
__device__ float g_bLi[450];
__device__ float g_bUi[750];

__device__ __forceinline__ float sigmoidf(float x) {
    return 1.0f / (1.0f + expf(-x));
}

// ---------------- weight stacking (gate-interleaved) ----------------
__global__ void prep_kernel(
    const float* __restrict__ Wi, const float* __restrict__ bi,
    const float* __restrict__ Wo, const float* __restrict__ bo,
    const float* __restrict__ Wu, const float* __restrict__ bu,
    const float* __restrict__ U0i, const float* __restrict__ U1i, const float* __restrict__ bbi,
    const float* __restrict__ U00f, const float* __restrict__ U01f,
    const float* __restrict__ U10f, const float* __restrict__ U11f, const float* __restrict__ bbf,
    const float* __restrict__ U0o, const float* __restrict__ U1o, const float* __restrict__ bbo,
    const float* __restrict__ U0u, const float* __restrict__ U1u, const float* __restrict__ bbu)
{
    int t = blockIdx.x * blockDim.x + threadIdx.x;
    int stride = gridDim.x * blockDim.x;

    // leaf weights: n = j*3 + g ; g: 0=i, 1=o, 2=u
    for (int idx = t; idx < 450 * EMBED; idx += stride) {
        int n = idx / EMBED, k = idx % EMBED;
        int j = n / 3, g = n % 3;
        const float* W = (g == 0) ? Wi : (g == 1) ? Wo : Wu;
        g_WLi[idx] = W[j * EMBED + k];
    }
    // inner weights: n = j*5 + g ; g: 0=i, 1=fl, 2=fr, 3=o, 4=u ; cols = [U0 | U1]
    for (int idx = t; idx < 750 * EMBED; idx += stride) {
        int n = idx / EMBED, k = idx % EMBED;
        int j = n / 5, g = n % 5;
        const float* U0; const float* U1;
        switch (g) {
            case 0:  U0 = U0i;  U1 = U1i;  break;
            case 1:  U0 = U00f; U1 = U01f; break;
            case 2:  U0 = U10f; U1 = U11f; break;
            case 3:  U0 = U0o;  U1 = U1o;  break;
            default: U0 = U0u;  U1 = U1u;  break;
        }
        g_WUi[idx] = (k < HIDDEN) ? U0[j * HIDDEN + k] : U1[j * HIDDEN + (k - HIDDEN)];
    }
    if (t < 450) {
        int j = t / 3, g = t % 3;
        g_bLi[t] = (g == 0) ? bi[j] : (g == 1) ? bo[j] : bu[j];
    }
    if (t < 750) {
        int j = t / 5, g = t % 5;
        g_bUi[t] = (g == 0) ? bbi[j] : (g <= 2) ? bbf[j] : (g == 3) ? bbo[j] : bbu[j];
    }
}

// ---------------- fused tiled GEMM + activation ----------------
// thread tile: ROWS rows x 1 j x GATES gates
// block: BJ*(BM/ROWS) threads ; tx = tid % BJ -> j ; ty = tid / BJ -> row group
template<int GATES, int MODE, int BM, int BJ, int ROWS>
__global__ __launch_bounds__(BJ * (BM / ROWS))
void fused_level(int s, int M,
                 const float* __restrict__ emb,
                 const int* __restrict__ words)
{
    constexpr int THREADS = BJ * (BM / ROWS);
    constexpr int WCOLS = BJ * GATES;
    constexpr int AELEMS = BM * BK;
    constexpr int WELEMS = WCOLS * BK;
    constexpr int LA = AELEMS / THREADS;            // exact: 5
    constexpr int LW = (WELEMS + THREADS - 1) / THREADS;

    __shared__ float As[BK][BM];
    __shared__ float Ws[BK][WCOLS];
    __shared__ int   rowOff[BM];

    const float* __restrict__ W     = (MODE == 0) ? g_WLi : g_WUi;
    const float* __restrict__ Abase = (MODE == 0) ? emb : (g_H + (2 * s + 1) * HIDDEN);
    const float* __restrict__ bias  = (MODE == 0) ? g_bLi : g_bUi;

    int bm = blockIdx.x * BM;
    int j0 = blockIdx.y * BJ;
    int n0 = j0 * GATES;
    int tid = threadIdx.x;
    int tx = tid % BJ, ty = tid / BJ;

    for (int e = tid; e < BM; e += THREADS) {
        int m = bm + e;
        int off = -1;
        if (m < M) {
            if (MODE == 0) off = words[LEAF_START + m] * EMBED;
            else           off = m * EMBED;   // children [lh|rh] contiguous
        }
        rowOff[e] = off;
    }
    __syncthreads();

    float acc[ROWS][GATES];
    #pragma unroll
    for (int i = 0; i < ROWS; i++)
        #pragma unroll
        for (int g = 0; g < GATES; g++)
            acc[i][g] = 0.0f;

    for (int k0 = 0; k0 < EMBED; k0 += BK) {
        #pragma unroll
        for (int l = 0; l < LA; l++) {
            int e = tid + l * THREADS;
            int ml = e / BK, kk = e % BK;
            int off = rowOff[ml];
            As[kk][ml] = (off >= 0) ? Abase[off + k0 + kk] : 0.0f;
        }
        #pragma unroll
        for (int l = 0; l < LW; l++) {
            int e = tid + l * THREADS;
            if (e < WELEMS) {
                int nl = e / BK, kk = e % BK;
                int n = n0 + nl;
                Ws[kk][nl] = (n < HIDDEN * GATES) ? W[n * EMBED + k0 + kk] : 0.0f;
            }
        }
        __syncthreads();

        #pragma unroll
        for (int kk = 0; kk < BK; kk++) {
            float a[ROWS], w[GATES];
            #pragma unroll
            for (int i = 0; i < ROWS; i++) a[i] = As[kk][ty * ROWS + i];
            #pragma unroll
            for (int g = 0; g < GATES; g++) w[g] = Ws[kk][tx * GATES + g];
            #pragma unroll
            for (int i = 0; i < ROWS; i++)
                #pragma unroll
                for (int g = 0; g < GATES; g++)
                    acc[i][g] += a[i] * w[g];
        }
        __syncthreads();
    }

    int j = j0 + tx;
    if (j >= HIDDEN) return;
    int nb = j * GATES;
    #pragma unroll
    for (int i = 0; i < ROWS; i++) {
        int m = bm + ty * ROWS + i;
        if (m >= M) continue;
        if (MODE == 0) {
            float ig = sigmoidf(acc[i][0] + bias[nb + 0]);
            float og = sigmoidf(acc[i][1] + bias[nb + 1]);
            float uv = tanhf   (acc[i][2] + bias[nb + 2]);
            float c = ig * uv;
            float h = og * tanhf(c);
            int node = LEAF_START + m;
            g_H[node * HIDDEN + j] = h;
            g_C[node * HIDDEN + j] = c;
        } else {
            float ig = sigmoidf(acc[i][0] + bias[nb + 0]);
            float fl = sigmoidf(acc[i][1] + bias[nb + 1]);
            float fr = sigmoidf(acc[i][2] + bias[nb + 2]);
            float og = sigmoidf(acc[i][3] + bias[nb + 3]);
            float uv = tanhf   (acc[i][4] + bias[nb + 4]);
            int node = s + m;
            float lc = g_C[(2 * node + 1) * HIDDEN + j];
            float rc = g_C[(2 * node + 2) * HIDDEN + j];
            float c = ig * uv + fl * lc + fr * rc;
            float h = og * tanhf(c);
            g_H[node * HIDDEN + j] = h;
            g_C[node * HIDDEN + j] = c;
        }
    }
}

// ---------------- warp-per-(node, j) kernel for tiny levels ----------------
__global__ void warp_level(int s, int M)
{
    int wid  = (blockIdx.x * blockDim.x + threadIdx.x) >> 5;
    int lane = threadIdx.x & 31;
    int m = wid / HIDDEN;
    int j = wid % HIDDEN;
    if (m >= M) return;

    const float* __restrict__ A  = g_H + (2 * s + 1 + 2 * m) * HIDDEN;  // 300 contiguous
    const float* __restrict__ Wr = g_WUi + (j * 5) * EMBED;

    float a0 = 0.f, a1 = 0.f, a2 = 0.f, a3 = 0.f, a4 = 0.f;
    #pragma unroll
    for (int kb = 0; kb < EMBED; kb += 32) {
        int k = kb + lane;
        float a = A[k];
        a0 += a * Wr[k];
        a1 += a * Wr[EMBED + k];
        a2 += a * Wr[2 * EMBED + k];
        a3 += a * Wr[3 * EMBED + k];
        a4 += a * Wr[4 * EMBED + k];
    }
    #pragma unroll
    for (int d = 16; d > 0; d >>= 1) {
        a0 += __shfl_xor_sync(0xffffffff, a0, d);
        a1 += __shfl_xor_sync(0xffffffff, a1, d);
        a2 += __shfl_xor_sync(0xffffffff, a2, d);
        a3 += __shfl_xor_sync(0xffffffff, a3, d);
        a4 += __shfl_xor_sync(0xffffffff, a4, d);
    }
    if (lane == 0) {
        int nb = j * 5;
        float ig = sigmoidf(a0 + g_bUi[nb + 0]);
        float fl = sigmoidf(a1 + g_bUi[nb + 1]);
        float fr = sigmoidf(a2 + g_bUi[nb + 2]);
        float og = sigmoidf(a3 + g_bUi[nb + 3]);
        float uv = tanhf   (a4 + g_bUi[nb + 4]);
        int node = s + m;
        float lc = g_C[(2 * node + 1) * HIDDEN + j];
        float rc = g_C[(2 * node + 2) * HIDDEN + j];
        float c = ig * uv + fl * lc + fr * rc;
        float h = og * tanhf(c);
        g_H[node * HIDDEN + j] = h;
        g_C[node * HIDDEN + j] = c;
    }
}

// ---------------- loss ----------------
__global__ void zero_out(float* out)
{
    if (threadIdx.x == 0 && blockIdx.x == 0) out[0] = 0.0f;
}

__global__ void loss_kernel(const float* __restrict__ Why,
                            const float* __restrict__ by,
                            const int*   __restrict__ scores,
                            float* __restrict__ out)
{
    int gw   = (blockIdx.x * blockDim.x + threadIdx.x) >> 5;
    int lane = threadIdx.x & 31;
    if (gw >= NN) return;

    const float* h = g_H + gw * HIDDEN;
    float logits[OUTC];
    #pragma unroll
    for (int o = 0; o < OUTC; o++) {
        float sacc = 0.0f;
        for (int k = lane; k < HIDDEN; k += 32)
            sacc += Why[o * HIDDEN + k] * h[k];
        #pragma unroll
        for (int d = 16; d > 0; d >>= 1)
            sacc += __shfl_xor_sync(0xffffffff, sacc, d);
        logits[o] = sacc + by[o];
    }
    if (lane == 0) {
        float mx = logits[0];
        #pragma unroll
        for (int o = 1; o < OUTC; o++) mx = fmaxf(mx, logits[o]);
        float se = 0.0f;
        #pragma unroll
        for (int o = 0; o < OUTC; o++) se += expf(logits[o] - mx);
        float lse = mx + logf(se);
        int sc = scores[gw];
        atomicAdd(out, lse - logits[sc]);
    }
}

// ---------------- launch ----------------
extern "C" void kernel_launch(void* const* d_in, const int* in_sizes, int n_in,
                              void* d_out, int out_size)
{
    const float* Wi   = (const float*)d_in[0];
    const float* bi   = (const float*)d_in[1];
    const float* Wo   = (const float*)d_in[2];
    const float* bo   = (const float*)d_in[3];
    const float* Wu   = (const float*)d_in[4];
    const float* bu   = (const float*)d_in[5];
    const float* U0i  = (const float*)d_in[6];
    const float* U1i  = (const float*)d_in[7];
    const float* bbi  = (const float*)d_in[8];
    const float* U00f = (const float*)d_in[9];
    const float* U01f = (const float*)d_in[10];
    const float* U10f = (const float*)d_in[11];
    const float* U11f = (const float*)d_in[12];
    const float* bbf  = (const float*)d_in[13];
    const float* U0o  = (const float*)d_in[14];
    const float* U1o  = (const float*)d_in[15];
    const float* bbo  = (const float*)d_in[16];
    const float* U0u  = (const float*)d_in[17];
    const float* U1u  = (const float*)d_in[18];
    const float* bbu  = (const float*)d_in[19];
    const float* Why  = (const float*)d_in[20];
    const float* by   = (const float*)d_in[21];
    const float* emb  = (const float*)d_in[22];
    const int*   scores = (const int*)d_in[23];
    const int*   words  = (const int*)d_in[24];

    float* out = (float*)d_out;

    zero_out<<<1, 32>>>(out);
    prep_kernel<<<240, 256>>>(Wi, bi, Wo, bo, Wu, bu,
                              U0i, U1i, bbi,
                              U00f, U01f, U10f, U11f, bbf,
                              U0o, U1o, bbo,
                              U0u, U1u, bbu);

    // leaf: M=4096, GATES=3, big config (BM=64, BJ=16, ROWS=4, 256 thr)
    {
        dim3 grid(LL / 64, (HIDDEN + 15) / 16);   // (64, 10)
        fused_level<3, 0, 64, 16, 4><<<grid, 256>>>(0, LL, emb, words);
    }

    // big inner levels d=11,10: BM=64, BJ=16, ROWS=4
    for (int d = 11; d >= 10; d--) {
        int s = (1 << d) - 1, M = 1 << d;
        dim3 grid(M / 64, (HIDDEN + 15) / 16);
        fused_level<5, 1, 64, 16, 4><<<grid, 256>>>(s, M, nullptr, nullptr);
    }

    // mid levels d=9..6: BM=32, BJ=8, ROWS=2 (128 thr)
    for (int d = 9; d >= 6; d--) {
        int s = (1 << d) - 1, M = 1 << d;
        dim3 grid(M / 32, (HIDDEN + 7) / 8);
        fused_level<5, 1, 32, 8, 2><<<grid, 128>>>(s, M, nullptr, nullptr);
    }

    // tiny levels d=5..0: warp per (node, j)
    for (int d = 5; d >= 0; d--) {
        int s = (1 << d) - 1, M = 1 << d;
        int warps = M * HIDDEN;
        int blocks = (warps + 7) / 8;
        warp_level<<<blocks, 256>>>(s, M);
    }

    // final loss over all 8191 nodes
    {
        int blocks = (NN + 7) / 8;
        loss_kernel<<<blocks, 256>>>(Why, by, scores, out);
    }
    (void)in_sizes; (void)n_in; (void)out_size;
}